// round 8
// baseline (speedup 1.0000x reference)
#include <cuda_runtime.h>
#include <cuda_bf16.h>
#include <math.h>
#include <stdint.h>

#define N_NODES   10000
#define N_EDGES_IN 160000
#define E_TOT     170000      // + self loops
#define IN_CH     4097
#define HID       512
#define HEADS     4
#define HC1       2048        // HEADS*HID
#define OUT_CH    256
#define N_GRAPHS  64
#define NEG_SLOPE 0.2f

// ---------------- scratch (device globals; no allocation allowed) ----------
__device__ __align__(16) float g_h1[(size_t)N_NODES * HC1];      // x @ W1
__device__ __align__(16) float g_h1agg[(size_t)N_NODES * HC1];   // layer1 out
__device__ __align__(16) float g_h2[(size_t)N_NODES * OUT_CH];   // h1agg @ W2
__device__ __align__(16) float g_out2[(size_t)N_NODES * OUT_CH]; // layer2 out
__device__ __align__(16) float g_asrc1[N_NODES * HEADS];
__device__ __align__(16) float g_adst1[N_NODES * HEADS];
__device__ __align__(16) float g_asrc2[N_NODES];
__device__ __align__(16) float g_adst2[N_NODES];
__device__ __align__(16) float g_alpha1[(size_t)E_TOT * HEADS];
__device__ __align__(16) float g_alpha2[E_TOT];
__device__ __align__(16) int   g_deg[N_NODES];
__device__ __align__(16) int   g_rowptr[N_NODES + 1];
__device__ __align__(16) int   g_cursor[N_NODES];
__device__ __align__(16) int   g_src[E_TOT];
__device__ __align__(16) int   g_dst[E_TOT];
__device__ __align__(16) int   g_csr_src[E_TOT];
__device__ __align__(16) float g_gsum[N_GRAPHS * OUT_CH];
__device__ __align__(16) float g_gcnt[N_GRAPHS];
__device__ int g_ei_is64;     // dtype flags (edge_index, batch)
__device__ int g_batch_is64;

static inline int cdiv(int a, int b) { return (a + b - 1) / b; }

__device__ __forceinline__ float wredmax(float v) {
#pragma unroll
    for (int o = 16; o; o >>= 1) v = fmaxf(v, __shfl_xor_sync(0xFFFFFFFFu, v, o));
    return v;
}
__device__ __forceinline__ float wredsum(float v) {
#pragma unroll
    for (int o = 16; o; o >>= 1) v += __shfl_xor_sync(0xFFFFFFFFu, v, o);
    return v;
}
__device__ __forceinline__ float lrelu(float x) {
    return x > 0.f ? x : NEG_SLOPE * x;
}

// ---------------- dtype detection -------------------------------------------
// int64 values < 2^31 (little-endian): odd int32 words are all 0.
// int32 random values in [0,10000): P(16 odd words all zero) ~ 1e-64.
__global__ void k_detect(const int* __restrict__ ei32,
                         const int* __restrict__ batch32) {
    if (threadIdx.x == 0) {
        int all0 = 1;
        for (int i = 1; i < 32; i += 2) all0 &= (ei32[i] == 0);
        g_ei_is64 = all0;
        int all0b = 1;
        for (int i = 1; i < 32; i += 2) all0b &= (batch32[N_NODES - 32 + i] == 0);
        g_batch_is64 = all0b;
    }
}

__device__ __forceinline__ int load_idx(const void* p, int i, int is64) {
    return is64 ? (int)((const long long*)p)[i] : ((const int*)p)[i];
}

// ---------------- graph prep ----------------------------------------------
__global__ void k_init() {
    int i = blockIdx.x * blockDim.x + threadIdx.x;
    if (i < N_NODES) g_deg[i] = 0;
    if (i < N_GRAPHS * OUT_CH) g_gsum[i] = 0.f;
    if (i < N_GRAPHS) g_gcnt[i] = 0.f;
}

__global__ void k_build(const void* __restrict__ ei) {
    int e = blockIdx.x * blockDim.x + threadIdx.x;
    if (e >= E_TOT) return;
    int is64 = g_ei_is64;
    int s, d;
    if (e < N_EDGES_IN) {
        s = load_idx(ei, e, is64);
        d = load_idx(ei, N_EDGES_IN + e, is64);
    } else {
        s = d = e - N_EDGES_IN;
    }
    g_src[e] = s;
    g_dst[e] = d;
    atomicAdd(&g_deg[d], 1);
}

// single-block exclusive scan of degrees -> rowptr, cursor
__global__ void k_scan() {
    __shared__ int sh[1024];
    __shared__ int carry;
    int t = threadIdx.x;
    if (t == 0) carry = 0;
    __syncthreads();
    for (int base = 0; base < N_NODES; base += 1024) {
        int i = base + t;
        int v = (i < N_NODES) ? g_deg[i] : 0;
        sh[t] = v;
        __syncthreads();
        for (int off = 1; off < 1024; off <<= 1) {
            int x = (t >= off) ? sh[t - off] : 0;
            __syncthreads();
            sh[t] += x;
            __syncthreads();
        }
        int excl = sh[t] - v;
        if (i < N_NODES) {
            g_rowptr[i] = carry + excl;
            g_cursor[i] = carry + excl;
        }
        __syncthreads();
        if (t == 0) carry += sh[1023];
        __syncthreads();
    }
    if (t == 0) g_rowptr[N_NODES] = carry;
}

__global__ void k_scatter() {
    int e = blockIdx.x * blockDim.x + threadIdx.x;
    if (e >= E_TOT) return;
    int d = g_dst[e];
    int slot = atomicAdd(&g_cursor[d], 1);
    g_csr_src[slot] = g_src[e];
}

// ---------------- split-bf16 tensor-core GEMM ------------------------------
// C[M,N] = A[M,K] @ B[K,N] in ~fp32 precision via hi/lo bf16 split:
//   A*B ~= Ah*Bh + Ah*Bl + Al*Bh   (lo*lo dropped, ~2^-17 rel)
// Block tile 128x128x32, 8 warps (2x4), warp tile 64x32, mma.m16n8k16.
#define SSTR 40   // smem row stride in bf16 elems (80B: conflict-free pattern)

__device__ __forceinline__ void mma_bf16(float* c, const unsigned* a,
                                         const unsigned* b) {
    asm volatile(
        "mma.sync.aligned.m16n8k16.row.col.f32.bf16.bf16.f32 "
        "{%0,%1,%2,%3}, {%4,%5,%6,%7}, {%8,%9}, {%0,%1,%2,%3};\n"
        : "+f"(c[0]), "+f"(c[1]), "+f"(c[2]), "+f"(c[3])
        : "r"(a[0]), "r"(a[1]), "r"(a[2]), "r"(a[3]), "r"(b[0]), "r"(b[1]));
}

__device__ __forceinline__ void split_bf16(float v, __nv_bfloat16& h,
                                           __nv_bfloat16& l) {
    h = __float2bfloat16_rn(v);
    l = __float2bfloat16_rn(v - __bfloat162float(h));
}

__device__ void mma_gemm_body(const float* __restrict__ A,
                              const float* __restrict__ B,
                              float* __restrict__ C,
                              int M, int N, int K) {
    __shared__ __nv_bfloat16 Ah[128][SSTR], Al[128][SSTR];
    __shared__ __nv_bfloat16 Bh[128][SSTR], Bl[128][SSTR];

    int tid = threadIdx.x;
    int lane = tid & 31, wid = tid >> 5;
    int wm = wid >> 2, wn = wid & 3;      // 2x4 warp grid
    int gq = lane >> 2, tg = lane & 3;    // groupID, thread-in-group
    int m0 = blockIdx.y * 128, n0 = blockIdx.x * 128;

    float acc[4][4][4];
#pragma unroll
    for (int i = 0; i < 4; i++)
#pragma unroll
        for (int j = 0; j < 4; j++)
#pragma unroll
            for (int r = 0; r < 4; r++) acc[i][j][r] = 0.f;

    int ntile = (K + 31) / 32;
    for (int kt = 0; kt < ntile; kt++) {
        int k0 = kt * 32;
        // A tile: coalesced rows; lane covers k-offset, 16 row-passes
        {
            int kc = lane;           // 0..31
            int r0 = tid >> 5;       // 0..7
#pragma unroll
            for (int i = 0; i < 16; i++) {
                int r = r0 + i * 8;
                int gm = m0 + r, gk = k0 + kc;
                float v = (gm < M && gk < K) ? A[(size_t)gm * K + gk] : 0.f;
                split_bf16(v, Ah[r][kc], Al[r][kc]);
            }
        }
        // B tile: stored transposed [n][k]; coalesced global reads along n
        {
            int nl = tid & 127;
            int kb = (tid >> 7) * 4;  // 0 or 4
#pragma unroll
            for (int p = 0; p < 4; p++) {
                int kl = kb + p * 8;
#pragma unroll
                for (int i = 0; i < 4; i++) {
                    int gk = k0 + kl + i;
                    float v = (gk < K) ? B[(size_t)gk * N + n0 + nl] : 0.f;
                    split_bf16(v, Bh[nl][kl + i], Bl[nl][kl + i]);
                }
            }
        }
        __syncthreads();

#pragma unroll
        for (int kk = 0; kk < 32; kk += 16) {
            unsigned ah[4][4], al[4][4], bh[4][2], bl[4][2];
#pragma unroll
            for (int i = 0; i < 4; i++) {
                int r = wm * 64 + i * 16;
                ah[i][0] = *(const unsigned*)&Ah[r + gq][kk + 2 * tg];
                ah[i][1] = *(const unsigned*)&Ah[r + gq + 8][kk + 2 * tg];
                ah[i][2] = *(const unsigned*)&Ah[r + gq][kk + 2 * tg + 8];
                ah[i][3] = *(const unsigned*)&Ah[r + gq + 8][kk + 2 * tg + 8];
                al[i][0] = *(const unsigned*)&Al[r + gq][kk + 2 * tg];
                al[i][1] = *(const unsigned*)&Al[r + gq + 8][kk + 2 * tg];
                al[i][2] = *(const unsigned*)&Al[r + gq][kk + 2 * tg + 8];
                al[i][3] = *(const unsigned*)&Al[r + gq + 8][kk + 2 * tg + 8];
            }
#pragma unroll
            for (int j = 0; j < 4; j++) {
                int c = wn * 32 + j * 8;
                bh[j][0] = *(const unsigned*)&Bh[c + gq][kk + 2 * tg];
                bh[j][1] = *(const unsigned*)&Bh[c + gq][kk + 2 * tg + 8];
                bl[j][0] = *(const unsigned*)&Bl[c + gq][kk + 2 * tg];
                bl[j][1] = *(const unsigned*)&Bl[c + gq][kk + 2 * tg + 8];
            }
#pragma unroll
            for (int i = 0; i < 4; i++)
#pragma unroll
                for (int j = 0; j < 4; j++) {
                    mma_bf16(acc[i][j], ah[i], bh[j]);
                    mma_bf16(acc[i][j], ah[i], bl[j]);
                    mma_bf16(acc[i][j], al[i], bh[j]);
                }
        }
        __syncthreads();
    }

    // epilogue
#pragma unroll
    for (int i = 0; i < 4; i++) {
#pragma unroll
        for (int j = 0; j < 4; j++) {
            int rm = m0 + wm * 64 + i * 16 + gq;
            int cn = n0 + wn * 32 + j * 8 + 2 * tg;
            if (rm < M) {
                float2 v = make_float2(acc[i][j][0], acc[i][j][1]);
                *(float2*)&C[(size_t)rm * N + cn] = v;
            }
            if (rm + 8 < M) {
                float2 v = make_float2(acc[i][j][2], acc[i][j][3]);
                *(float2*)&C[(size_t)(rm + 8) * N + cn] = v;
            }
        }
    }
}

__global__ __launch_bounds__(256, 1) void k_gemm1(const float* __restrict__ x,
                                                  const float* __restrict__ W1) {
    mma_gemm_body(x, W1, g_h1, N_NODES, HC1, IN_CH);
}
__global__ __launch_bounds__(256, 1) void k_gemm2(const float* __restrict__ W2) {
    mma_gemm_body(g_h1agg, W2, g_h2, N_NODES, OUT_CH, HC1);
}

// ---------------- attention logits -----------------------------------------
__global__ void k_att1(const float* __restrict__ att_src,
                       const float* __restrict__ att_dst) {
    int n = blockIdx.x;
    int w = threadIdx.x >> 5, lane = threadIdx.x & 31;
    const float* hrow = g_h1 + (size_t)n * HC1 + w * HID;
    const float* as = att_src + w * HID;
    const float* ad = att_dst + w * HID;
    float s = 0.f, d = 0.f;
    for (int c = lane; c < HID; c += 32) {
        float h = hrow[c];
        s += h * as[c];
        d += h * ad[c];
    }
    s = wredsum(s);
    d = wredsum(d);
    if (lane == 0) {
        g_asrc1[n * HEADS + w] = s;
        g_adst1[n * HEADS + w] = d;
    }
}

__global__ void k_att2(const float* __restrict__ att_src,
                       const float* __restrict__ att_dst) {
    int node = blockIdx.x * 8 + (threadIdx.x >> 5);
    int lane = threadIdx.x & 31;
    if (node >= N_NODES) return;
    const float* hrow = g_h2 + (size_t)node * OUT_CH;
    float s = 0.f, d = 0.f;
    for (int c = lane; c < OUT_CH; c += 32) {
        float h = hrow[c];
        s += h * att_src[c];
        d += h * att_dst[c];
    }
    s = wredsum(s);
    d = wredsum(d);
    if (lane == 0) {
        g_asrc2[node] = s;
        g_adst2[node] = d;
    }
}

// ---------------- segment softmax ------------------------------------------
__global__ void k_softmax1() {
    int node = blockIdx.x * 8 + (threadIdx.x >> 5);
    int lane = threadIdx.x & 31;
    if (node >= N_NODES) return;
    int s0 = g_rowptr[node], s1 = g_rowptr[node + 1];
#pragma unroll
    for (int h = 0; h < HEADS; h++) {
        float ad = g_adst1[node * HEADS + h];
        float m = -INFINITY;
        for (int s = s0 + lane; s < s1; s += 32)
            m = fmaxf(m, lrelu(g_asrc1[g_csr_src[s] * HEADS + h] + ad));
        m = wredmax(m);
        float sum = 0.f;
        for (int s = s0 + lane; s < s1; s += 32)
            sum += expf(lrelu(g_asrc1[g_csr_src[s] * HEADS + h] + ad) - m);
        sum = wredsum(sum);
        float inv = 1.f / (sum + 1e-16f);
        for (int s = s0 + lane; s < s1; s += 32)
            g_alpha1[(size_t)s * HEADS + h] =
                expf(lrelu(g_asrc1[g_csr_src[s] * HEADS + h] + ad) - m) * inv;
    }
}

__global__ void k_softmax2() {
    int node = blockIdx.x * 8 + (threadIdx.x >> 5);
    int lane = threadIdx.x & 31;
    if (node >= N_NODES) return;
    int s0 = g_rowptr[node], s1 = g_rowptr[node + 1];
    float ad = g_adst2[node];
    float m = -INFINITY;
    for (int s = s0 + lane; s < s1; s += 32)
        m = fmaxf(m, lrelu(g_asrc2[g_csr_src[s]] + ad));
    m = wredmax(m);
    float sum = 0.f;
    for (int s = s0 + lane; s < s1; s += 32)
        sum += expf(lrelu(g_asrc2[g_csr_src[s]] + ad) - m);
    sum = wredsum(sum);
    float inv = 1.f / (sum + 1e-16f);
    for (int s = s0 + lane; s < s1; s += 32)
        g_alpha2[s] = expf(lrelu(g_asrc2[g_csr_src[s]] + ad) - m) * inv;
}

// ---------------- aggregation ----------------------------------------------
__global__ __launch_bounds__(256) void k_agg1(const float* __restrict__ b1) {
    int n = blockIdx.x;
    int t = threadIdx.x;
    int s0 = g_rowptr[n], s1 = g_rowptr[n + 1];
    float acc[8];
#pragma unroll
    for (int j = 0; j < 8; j++) acc[j] = 0.f;
    for (int s = s0; s < s1; s++) {
        int src = g_csr_src[s];
        float4 al4 = ((const float4*)g_alpha1)[s];  // 4 heads of edge s
        float al[4] = {al4.x, al4.y, al4.z, al4.w};
        const float* row = g_h1 + (size_t)src * HC1;
#pragma unroll
        for (int j = 0; j < 8; j++)
            acc[j] += al[j >> 1] * row[t + 256 * j];
    }
    float* out = g_h1agg + (size_t)n * HC1;
#pragma unroll
    for (int j = 0; j < 8; j++) {
        int c = t + 256 * j;
        out[c] = fmaxf(acc[j] + b1[c], 0.f);  // + bias, then ReLU
    }
}

__global__ __launch_bounds__(256) void k_agg2(const float* __restrict__ b2) {
    int n = blockIdx.x;
    int t = threadIdx.x;
    int s0 = g_rowptr[n], s1 = g_rowptr[n + 1];
    float acc = 0.f;
    for (int s = s0; s < s1; s++) {
        int src = g_csr_src[s];
        acc += g_alpha2[s] * g_h2[(size_t)src * OUT_CH + t];
    }
    g_out2[(size_t)n * OUT_CH + t] = acc + b2[t];
}

// ---------------- mean pool -------------------------------------------------
__global__ void k_pool(const void* __restrict__ batch) {
    int n = blockIdx.x;
    int t = threadIdx.x;
    int g = load_idx(batch, n, g_batch_is64);
    atomicAdd(&g_gsum[g * OUT_CH + t], g_out2[(size_t)n * OUT_CH + t]);
    if (t == 0) atomicAdd(&g_gcnt[g], 1.f);
}

__global__ void k_final(float* __restrict__ out) {
    int g = blockIdx.x;
    int t = threadIdx.x;
    out[g * OUT_CH + t] = g_gsum[g * OUT_CH + t] / fmaxf(g_gcnt[g], 1.f);
}

// ---------------- launch ----------------------------------------------------
extern "C" void kernel_launch(void* const* d_in, const int* in_sizes, int n_in,
                              void* d_out, int out_size) {
    const float* x        = (const float*)d_in[0];
    const void*  ei       = d_in[1];
    const void*  batch    = d_in[2];
    const float* W1       = (const float*)d_in[3];
    const float* att_src1 = (const float*)d_in[4];
    const float* att_dst1 = (const float*)d_in[5];
    const float* b1       = (const float*)d_in[6];
    const float* W2       = (const float*)d_in[7];
    const float* att_src2 = (const float*)d_in[8];
    const float* att_dst2 = (const float*)d_in[9];
    const float* b2       = (const float*)d_in[10];
    float*       out      = (float*)d_out;

    k_detect<<<1, 32>>>((const int*)ei, (const int*)batch);
    k_init<<<cdiv(N_GRAPHS * OUT_CH, 256), 256>>>();
    k_build<<<cdiv(E_TOT, 256), 256>>>(ei);
    k_scan<<<1, 1024>>>();
    k_scatter<<<cdiv(E_TOT, 256), 256>>>();

    // GEMM1: h1 = x @ W1   [10000,4097]@[4097,2048]  (split-bf16 tensor cores)
    k_gemm1<<<dim3(HC1 / 128, cdiv(N_NODES, 128)), 256>>>(x, W1);
    k_att1<<<N_NODES, 128>>>(att_src1, att_dst1);
    k_softmax1<<<cdiv(N_NODES, 8), 256>>>();
    k_agg1<<<N_NODES, 256>>>(b1);

    // GEMM2: h2 = h1agg @ W2   [10000,2048]@[2048,256]
    k_gemm2<<<dim3(OUT_CH / 128, cdiv(N_NODES, 128)), 256>>>(W2);
    k_att2<<<cdiv(N_NODES, 8), 256>>>(att_src2, att_dst2);
    k_softmax2<<<cdiv(N_NODES, 8), 256>>>();
    k_agg2<<<N_NODES, 256>>>(b2);

    k_pool<<<N_NODES, 256>>>(batch);
    k_final<<<N_GRAPHS, OUT_CH>>>(out);
}

// round 12
// speedup vs baseline: 1.5744x; 1.5744x over previous
#include <cuda_runtime.h>
#include <cuda_bf16.h>
#include <math.h>
#include <stdint.h>

#define N_NODES   10000
#define N_EDGES_IN 160000
#define E_TOT     170000      // + self loops
#define IN_CH     4097
#define HID       512
#define HEADS     4
#define HC1       2048        // HEADS*HID
#define OUT_CH    256
#define N_GRAPHS  64
#define NEG_SLOPE 0.2f

// ---------------- scratch (device globals; no allocation allowed) ----------
__device__ __align__(16) float g_h1[(size_t)N_NODES * HC1];      // x @ W1
__device__ __align__(16) float g_h1agg[(size_t)N_NODES * HC1];   // layer1 out
__device__ __align__(16) float g_h2[(size_t)N_NODES * OUT_CH];   // h1agg @ W2
__device__ __align__(16) float g_out2[(size_t)N_NODES * OUT_CH]; // layer2 out
__device__ __align__(16) float g_asrc1[N_NODES * HEADS];
__device__ __align__(16) float g_adst1[N_NODES * HEADS];
__device__ __align__(16) float g_asrc2[N_NODES];
__device__ __align__(16) float g_adst2[N_NODES];
__device__ __align__(16) float g_alpha1[(size_t)E_TOT * HEADS];
__device__ __align__(16) float g_alpha2[E_TOT];
__device__ __align__(16) int   g_deg[N_NODES];
__device__ __align__(16) int   g_rowptr[N_NODES + 1];
__device__ __align__(16) int   g_cursor[N_NODES];
__device__ __align__(16) int   g_src[E_TOT];
__device__ __align__(16) int   g_dst[E_TOT];
__device__ __align__(16) int   g_csr_src[E_TOT];
__device__ __align__(16) float g_gsum[N_GRAPHS * OUT_CH];
__device__ __align__(16) float g_gcnt[N_GRAPHS];
__device__ int g_ei_is64;     // dtype flags (edge_index, batch)
__device__ int g_batch_is64;

static inline int cdiv(int a, int b) { return (a + b - 1) / b; }

__device__ __forceinline__ float wredmax(float v) {
#pragma unroll
    for (int o = 16; o; o >>= 1) v = fmaxf(v, __shfl_xor_sync(0xFFFFFFFFu, v, o));
    return v;
}
__device__ __forceinline__ float wredsum(float v) {
#pragma unroll
    for (int o = 16; o; o >>= 1) v += __shfl_xor_sync(0xFFFFFFFFu, v, o);
    return v;
}
__device__ __forceinline__ float lrelu(float x) {
    return x > 0.f ? x : NEG_SLOPE * x;
}

// ---------------- dtype detection -------------------------------------------
__global__ void k_detect(const int* __restrict__ ei32,
                         const int* __restrict__ batch32) {
    if (threadIdx.x == 0) {
        int all0 = 1;
        for (int i = 1; i < 32; i += 2) all0 &= (ei32[i] == 0);
        g_ei_is64 = all0;
        int all0b = 1;
        for (int i = 1; i < 32; i += 2) all0b &= (batch32[N_NODES - 32 + i] == 0);
        g_batch_is64 = all0b;
    }
}

__device__ __forceinline__ int load_idx(const void* p, int i, int is64) {
    return is64 ? (int)((const long long*)p)[i] : ((const int*)p)[i];
}

// ---------------- graph prep ----------------------------------------------
__global__ void k_init() {
    int i = blockIdx.x * blockDim.x + threadIdx.x;
    if (i < N_NODES) g_deg[i] = 0;
    if (i < N_GRAPHS * OUT_CH) g_gsum[i] = 0.f;
    if (i < N_GRAPHS) g_gcnt[i] = 0.f;
}

__global__ void k_build(const void* __restrict__ ei) {
    int e = blockIdx.x * blockDim.x + threadIdx.x;
    if (e >= E_TOT) return;
    int is64 = g_ei_is64;
    int s, d;
    if (e < N_EDGES_IN) {
        s = load_idx(ei, e, is64);
        d = load_idx(ei, N_EDGES_IN + e, is64);
    } else {
        s = d = e - N_EDGES_IN;
    }
    g_src[e] = s;
    g_dst[e] = d;
    atomicAdd(&g_deg[d], 1);
}

__global__ void k_scan() {
    __shared__ int sh[1024];
    __shared__ int carry;
    int t = threadIdx.x;
    if (t == 0) carry = 0;
    __syncthreads();
    for (int base = 0; base < N_NODES; base += 1024) {
        int i = base + t;
        int v = (i < N_NODES) ? g_deg[i] : 0;
        sh[t] = v;
        __syncthreads();
        for (int off = 1; off < 1024; off <<= 1) {
            int x = (t >= off) ? sh[t - off] : 0;
            __syncthreads();
            sh[t] += x;
            __syncthreads();
        }
        int excl = sh[t] - v;
        if (i < N_NODES) {
            g_rowptr[i] = carry + excl;
            g_cursor[i] = carry + excl;
        }
        __syncthreads();
        if (t == 0) carry += sh[1023];
        __syncthreads();
    }
    if (t == 0) g_rowptr[N_NODES] = carry;
}

__global__ void k_scatter() {
    int e = blockIdx.x * blockDim.x + threadIdx.x;
    if (e >= E_TOT) return;
    int d = g_dst[e];
    int slot = atomicAdd(&g_cursor[d], 1);
    g_csr_src[slot] = g_src[e];
}

// ---------------- split-bf16 tensor-core GEMM ------------------------------
// C = A@B via hi/lo bf16 split (Ah*Bh + Ah*Bl + Al*Bh), 128x128x32 tiles,
// 8 warps, mma.m16n8k16, ldmatrix fragment loads, register-prefetch pipeline.
#define SSTR 40   // smem row stride in bf16 (80B): 8-row groups conflict-free

__device__ __forceinline__ void mma_bf16(float* c, const unsigned* a,
                                         const unsigned* b) {
    asm volatile(
        "mma.sync.aligned.m16n8k16.row.col.f32.bf16.bf16.f32 "
        "{%0,%1,%2,%3}, {%4,%5,%6,%7}, {%8,%9}, {%0,%1,%2,%3};\n"
        : "+f"(c[0]), "+f"(c[1]), "+f"(c[2]), "+f"(c[3])
        : "r"(a[0]), "r"(a[1]), "r"(a[2]), "r"(a[3]), "r"(b[0]), "r"(b[1]));
}

__device__ __forceinline__ void ldsm_x4(unsigned* r, const void* p) {
    unsigned a = (unsigned)__cvta_generic_to_shared(p);
    asm volatile("ldmatrix.sync.aligned.m8n8.x4.shared.b16 {%0,%1,%2,%3}, [%4];"
                 : "=r"(r[0]), "=r"(r[1]), "=r"(r[2]), "=r"(r[3]) : "r"(a));
}
__device__ __forceinline__ void ldsm_x2(unsigned* r, const void* p) {
    unsigned a = (unsigned)__cvta_generic_to_shared(p);
    asm volatile("ldmatrix.sync.aligned.m8n8.x2.shared.b16 {%0,%1}, [%2];"
                 : "=r"(r[0]), "=r"(r[1]) : "r"(a));
}

__device__ __forceinline__ void split_bf16(float v, __nv_bfloat16& h,
                                           __nv_bfloat16& l) {
    h = __float2bfloat16_rn(v);
    l = __float2bfloat16_rn(v - __bfloat162float(h));
}

__device__ void mma_gemm_body(const float* __restrict__ A,
                              const float* __restrict__ B,
                              float* __restrict__ C,
                              int M, int N, int K) {
    __shared__ __align__(16) __nv_bfloat16 Ah[128][SSTR], Al[128][SSTR];
    __shared__ __align__(16) __nv_bfloat16 Bh[128][SSTR], Bl[128][SSTR];

    int tid = threadIdx.x;
    int lane = tid & 31, wid = tid >> 5;
    int wm = wid >> 2, wn = wid & 3;      // 2x4 warp grid
    int gq = lane >> 2, tg = lane & 3;
    int m0 = blockIdx.y * 128, n0 = blockIdx.x * 128;

    float acc[4][4][4];
#pragma unroll
    for (int i = 0; i < 4; i++)
#pragma unroll
        for (int j = 0; j < 4; j++)
#pragma unroll
            for (int r = 0; r < 4; r++) acc[i][j][r] = 0.f;

    // prefetch registers
    float pa[16], pb[16];
    int a_kc = lane;            // A: k-offset within tile
    int a_r0 = tid >> 5;        // A: row start (stride 8)
    int b_nl = tid & 127;       // B: n within tile
    int b_kb = (tid >> 7) * 4;  // B: k base (0 or 4)

    auto load_tile = [&](int k0) {
#pragma unroll
        for (int i = 0; i < 16; i++) {
            int gm = m0 + a_r0 + i * 8, gk = k0 + a_kc;
            pa[i] = (gm < M && gk < K) ? A[(size_t)gm * K + gk] : 0.f;
        }
#pragma unroll
        for (int p = 0; p < 4; p++)
#pragma unroll
            for (int q = 0; q < 4; q++) {
                int gk = k0 + b_kb + p * 8 + q;
                pb[p * 4 + q] = (gk < K) ? B[(size_t)gk * N + n0 + b_nl] : 0.f;
            }
    };
    auto store_tile = [&]() {
#pragma unroll
        for (int i = 0; i < 16; i++)
            split_bf16(pa[i], Ah[a_r0 + i * 8][a_kc], Al[a_r0 + i * 8][a_kc]);
#pragma unroll
        for (int p = 0; p < 4; p++)
#pragma unroll
            for (int q = 0; q < 4; q++) {
                int kl = b_kb + p * 8 + q;
                split_bf16(pb[p * 4 + q], Bh[b_nl][kl], Bl[b_nl][kl]);
            }
    };

    int ntile = (K + 31) / 32;
    load_tile(0);
    for (int kt = 0; kt < ntile; kt++) {
        store_tile();
        __syncthreads();
        if (kt + 1 < ntile) load_tile((kt + 1) * 32);  // overlap with compute

#pragma unroll
        for (int kk = 0; kk < 32; kk += 16) {
            unsigned ah[4][4], al[4][4], bh[4][2], bl[4][2];
            int arow = wm * 64 + (lane & 15);
            int acol = kk + ((lane >> 4) << 3);
#pragma unroll
            for (int i = 0; i < 4; i++) {
                ldsm_x4(ah[i], &Ah[arow + i * 16][acol]);
                ldsm_x4(al[i], &Al[arow + i * 16][acol]);
            }
            int brow = wn * 32 + (lane & 7);
            int bcol = kk + (((lane >> 3) & 1) << 3);
#pragma unroll
            for (int j = 0; j < 4; j++) {
                ldsm_x2(bh[j], &Bh[brow + j * 8][bcol]);
                ldsm_x2(bl[j], &Bl[brow + j * 8][bcol]);
            }
#pragma unroll
            for (int i = 0; i < 4; i++)
#pragma unroll
                for (int j = 0; j < 4; j++) {
                    mma_bf16(acc[i][j], ah[i], bh[j]);
                    mma_bf16(acc[i][j], ah[i], bl[j]);
                    mma_bf16(acc[i][j], al[i], bh[j]);
                }
        }
        __syncthreads();
    }

    // epilogue
#pragma unroll
    for (int i = 0; i < 4; i++) {
#pragma unroll
        for (int j = 0; j < 4; j++) {
            int rm = m0 + wm * 64 + i * 16 + gq;
            int cn = n0 + wn * 32 + j * 8 + 2 * tg;
            if (rm < M) {
                float2 v = make_float2(acc[i][j][0], acc[i][j][1]);
                *(float2*)&C[(size_t)rm * N + cn] = v;
            }
            if (rm + 8 < M) {
                float2 v = make_float2(acc[i][j][2], acc[i][j][3]);
                *(float2*)&C[(size_t)(rm + 8) * N + cn] = v;
            }
        }
    }
}

__global__ __launch_bounds__(256, 1) void k_gemm1(const float* __restrict__ x,
                                                  const float* __restrict__ W1) {
    mma_gemm_body(x, W1, g_h1, N_NODES, HC1, IN_CH);
}
__global__ __launch_bounds__(256, 1) void k_gemm2(const float* __restrict__ W2) {
    mma_gemm_body(g_h1agg, W2, g_h2, N_NODES, OUT_CH, HC1);
}

// ---------------- attention logits -----------------------------------------
__global__ void k_att1(const float* __restrict__ att_src,
                       const float* __restrict__ att_dst) {
    int n = blockIdx.x;
    int w = threadIdx.x >> 5, lane = threadIdx.x & 31;
    const float* hrow = g_h1 + (size_t)n * HC1 + w * HID;
    const float* as = att_src + w * HID;
    const float* ad = att_dst + w * HID;
    float s = 0.f, d = 0.f;
    for (int c = lane; c < HID; c += 32) {
        float h = hrow[c];
        s += h * as[c];
        d += h * ad[c];
    }
    s = wredsum(s);
    d = wredsum(d);
    if (lane == 0) {
        g_asrc1[n * HEADS + w] = s;
        g_adst1[n * HEADS + w] = d;
    }
}

__global__ void k_att2(const float* __restrict__ att_src,
                       const float* __restrict__ att_dst) {
    int node = blockIdx.x * 8 + (threadIdx.x >> 5);
    int lane = threadIdx.x & 31;
    if (node >= N_NODES) return;
    const float* hrow = g_h2 + (size_t)node * OUT_CH;
    float s = 0.f, d = 0.f;
    for (int c = lane; c < OUT_CH; c += 32) {
        float h = hrow[c];
        s += h * att_src[c];
        d += h * att_dst[c];
    }
    s = wredsum(s);
    d = wredsum(d);
    if (lane == 0) {
        g_asrc2[node] = s;
        g_adst2[node] = d;
    }
}

// ---------------- segment softmax ------------------------------------------
__global__ void k_softmax1() {
    int node = blockIdx.x * 8 + (threadIdx.x >> 5);
    int lane = threadIdx.x & 31;
    if (node >= N_NODES) return;
    int s0 = g_rowptr[node], s1 = g_rowptr[node + 1];
#pragma unroll
    for (int h = 0; h < HEADS; h++) {
        float ad = g_adst1[node * HEADS + h];
        float m = -INFINITY;
        for (int s = s0 + lane; s < s1; s += 32)
            m = fmaxf(m, lrelu(g_asrc1[g_csr_src[s] * HEADS + h] + ad));
        m = wredmax(m);
        float sum = 0.f;
        for (int s = s0 + lane; s < s1; s += 32)
            sum += expf(lrelu(g_asrc1[g_csr_src[s] * HEADS + h] + ad) - m);
        sum = wredsum(sum);
        float inv = 1.f / (sum + 1e-16f);
        for (int s = s0 + lane; s < s1; s += 32)
            g_alpha1[(size_t)s * HEADS + h] =
                expf(lrelu(g_asrc1[g_csr_src[s] * HEADS + h] + ad) - m) * inv;
    }
}

__global__ void k_softmax2() {
    int node = blockIdx.x * 8 + (threadIdx.x >> 5);
    int lane = threadIdx.x & 31;
    if (node >= N_NODES) return;
    int s0 = g_rowptr[node], s1 = g_rowptr[node + 1];
    float ad = g_adst2[node];
    float m = -INFINITY;
    for (int s = s0 + lane; s < s1; s += 32)
        m = fmaxf(m, lrelu(g_asrc2[g_csr_src[s]] + ad));
    m = wredmax(m);
    float sum = 0.f;
    for (int s = s0 + lane; s < s1; s += 32)
        sum += expf(lrelu(g_asrc2[g_csr_src[s]] + ad) - m);
    sum = wredsum(sum);
    float inv = 1.f / (sum + 1e-16f);
    for (int s = s0 + lane; s < s1; s += 32)
        g_alpha2[s] = expf(lrelu(g_asrc2[g_csr_src[s]] + ad) - m) * inv;
}

// ---------------- aggregation ----------------------------------------------
__global__ __launch_bounds__(256) void k_agg1(const float* __restrict__ b1) {
    int n = blockIdx.x;
    int t = threadIdx.x;
    int s0 = g_rowptr[n], s1 = g_rowptr[n + 1];
    float acc[8];
#pragma unroll
    for (int j = 0; j < 8; j++) acc[j] = 0.f;
    for (int s = s0; s < s1; s++) {
        int src = g_csr_src[s];
        float4 al4 = ((const float4*)g_alpha1)[s];  // 4 heads of edge s
        float al[4] = {al4.x, al4.y, al4.z, al4.w};
        const float* row = g_h1 + (size_t)src * HC1;
#pragma unroll
        for (int j = 0; j < 8; j++)
            acc[j] += al[j >> 1] * row[t + 256 * j];
    }
    float* out = g_h1agg + (size_t)n * HC1;
#pragma unroll
    for (int j = 0; j < 8; j++) {
        int c = t + 256 * j;
        out[c] = fmaxf(acc[j] + b1[c], 0.f);  // + bias, then ReLU
    }
}

__global__ __launch_bounds__(256) void k_agg2(const float* __restrict__ b2) {
    int n = blockIdx.x;
    int t = threadIdx.x;
    int s0 = g_rowptr[n], s1 = g_rowptr[n + 1];
    float acc = 0.f;
    for (int s = s0; s < s1; s++) {
        int src = g_csr_src[s];
        acc += g_alpha2[s] * g_h2[(size_t)src * OUT_CH + t];
    }
    g_out2[(size_t)n * OUT_CH + t] = acc + b2[t];
}

// ---------------- mean pool -------------------------------------------------
__global__ void k_pool(const void* __restrict__ batch) {
    int n = blockIdx.x;
    int t = threadIdx.x;
    int g = load_idx(batch, n, g_batch_is64);
    atomicAdd(&g_gsum[g * OUT_CH + t], g_out2[(size_t)n * OUT_CH + t]);
    if (t == 0) atomicAdd(&g_gcnt[g], 1.f);
}

__global__ void k_final(float* __restrict__ out) {
    int g = blockIdx.x;
    int t = threadIdx.x;
    out[g * OUT_CH + t] = g_gsum[g * OUT_CH + t] / fmaxf(g_gcnt[g], 1.f);
}

// ---------------- launch ----------------------------------------------------
extern "C" void kernel_launch(void* const* d_in, const int* in_sizes, int n_in,
                              void* d_out, int out_size) {
    const float* x        = (const float*)d_in[0];
    const void*  ei       = d_in[1];
    const void*  batch    = d_in[2];
    const float* W1       = (const float*)d_in[3];
    const float* att_src1 = (const float*)d_in[4];
    const float* att_dst1 = (const float*)d_in[5];
    const float* b1       = (const float*)d_in[6];
    const float* W2       = (const float*)d_in[7];
    const float* att_src2 = (const float*)d_in[8];
    const float* att_dst2 = (const float*)d_in[9];
    const float* b2       = (const float*)d_in[10];
    float*       out      = (float*)d_out;

    k_detect<<<1, 32>>>((const int*)ei, (const int*)batch);
    k_init<<<cdiv(N_GRAPHS * OUT_CH, 256), 256>>>();
    k_build<<<cdiv(E_TOT, 256), 256>>>(ei);
    k_scan<<<1, 1024>>>();
    k_scatter<<<cdiv(E_TOT, 256), 256>>>();

    // GEMM1: h1 = x @ W1   [10000,4097]@[4097,2048]  (split-bf16 tensor cores)
    k_gemm1<<<dim3(HC1 / 128, cdiv(N_NODES, 128)), 256>>>(x, W1);
    k_att1<<<N_NODES, 128>>>(att_src1, att_dst1);
    k_softmax1<<<cdiv(N_NODES, 8), 256>>>();
    k_agg1<<<N_NODES, 256>>>(b1);

    // GEMM2: h2 = h1agg @ W2   [10000,2048]@[2048,256]
    k_gemm2<<<dim3(OUT_CH / 128, cdiv(N_NODES, 128)), 256>>>(W2);
    k_att2<<<cdiv(N_NODES, 8), 256>>>(att_src2, att_dst2);
    k_softmax2<<<cdiv(N_NODES, 8), 256>>>();
    k_agg2<<<N_NODES, 256>>>(b2);

    k_pool<<<N_NODES, 256>>>(batch);
    k_final<<<N_GRAPHS, OUT_CH>>>(out);
}